// round 9
// baseline (speedup 1.0000x reference)
#include <cuda_runtime.h>
#include <cuda_bf16.h>
#include <math.h>
#include <stdint.h>

#define T_TOK 2048
#define DDIM  2048
#define FDIM  4096
#define NEXP  8

// ---------- gu geometry: KCHUNK 16, NSTG 4, stride 48 B ----------
#define GU_NSTG 4
#define GU_KC   16
#define GU_AST  48
#define GU_ASTG (128 * GU_AST)              // 6144
#define GU_BSTG (128 * GU_AST)              // 6144
#define GU_AHI  0
#define GU_ALO  (GU_NSTG * GU_ASTG)         // 24576
#define GU_BHI  (2 * GU_NSTG * GU_ASTG)     // 49152
#define GU_BLO  (GU_BHI + GU_NSTG * GU_BSTG)// 73728
#define SMEM_GU (GU_BLO + GU_NSTG * GU_BSTG)// 98304

// ---------- dn geometry: KCHUNK 32, NSTG 3, stride 80 B ----------
#define DN_NSTG 3
#define DN_KC   32
#define DN_AST  80
#define DN_ASTG (128 * DN_AST)              // 10240
#define DN_BSTG (64 * DN_AST)               // 5120
#define DN_AHI  0
#define DN_ALO  (DN_NSTG * DN_ASTG)         // 30720
#define DN_BHI  (2 * DN_NSTG * DN_ASTG)     // 61440
#define DN_BLO  (DN_BHI + DN_NSTG * DN_BSTG)// 76800
#define SMEM_DN (DN_BLO + DN_NSTG * DN_BSTG)// 92160

// ---- static scratch ----
__device__ int   g_cnt[NEXP];
__device__ int   g_eid[T_TOK];
__device__ float g_w[T_TOK];
__device__ int   g_list[NEXP * T_TOK];
__device__ __nv_bfloat16 g_xhi[(size_t)T_TOK * DDIM];
__device__ __nv_bfloat16 g_xlo[(size_t)T_TOK * DDIM];
__device__ __nv_bfloat16 g_hhi[(size_t)T_TOK * FDIM];
__device__ __nv_bfloat16 g_hlo[(size_t)T_TOK * FDIM];
__device__ __nv_bfloat16 g_hshi[(size_t)T_TOK * FDIM];
__device__ __nv_bfloat16 g_hslo[(size_t)T_TOK * FDIM];
// transposed, pre-split weights: [e][n][k]
__device__ __nv_bfloat16 g_wgThi[(size_t)NEXP * FDIM * DDIM];
__device__ __nv_bfloat16 g_wgTlo[(size_t)NEXP * FDIM * DDIM];
__device__ __nv_bfloat16 g_wuThi[(size_t)NEXP * FDIM * DDIM];
__device__ __nv_bfloat16 g_wuTlo[(size_t)NEXP * FDIM * DDIM];
__device__ __nv_bfloat16 g_wdThi[(size_t)NEXP * DDIM * FDIM];
__device__ __nv_bfloat16 g_wdTlo[(size_t)NEXP * DDIM * FDIM];
__device__ __nv_bfloat16 g_wsgThi[(size_t)FDIM * DDIM];
__device__ __nv_bfloat16 g_wsgTlo[(size_t)FDIM * DDIM];
__device__ __nv_bfloat16 g_wsuThi[(size_t)FDIM * DDIM];
__device__ __nv_bfloat16 g_wsuTlo[(size_t)FDIM * DDIM];
__device__ __nv_bfloat16 g_wsdThi[(size_t)DDIM * FDIM];
__device__ __nv_bfloat16 g_wsdTlo[(size_t)DDIM * FDIM];

// ---- helpers ----
__device__ __forceinline__ uint32_t smem_u32(const void* p) {
    uint32_t a;
    asm("{ .reg .u64 t; cvta.to.shared.u64 t, %1; cvt.u32.u64 %0, t; }"
        : "=r"(a) : "l"(p));
    return a;
}

__device__ __forceinline__ void cpa16(uint32_t dst, const void* src, int srcsz) {
    asm volatile("cp.async.cg.shared.global [%0], [%1], 16, %2;"
                 :: "r"(dst), "l"(src), "r"(srcsz) : "memory");
}
#define CP_COMMIT() asm volatile("cp.async.commit_group;" ::: "memory")

#define MMA_BF16(d, a, b) \
    asm volatile("mma.sync.aligned.m16n8k16.row.col.f32.bf16.bf16.f32 " \
        "{%0,%1,%2,%3}, {%4,%5,%6,%7}, {%8,%9}, {%0,%1,%2,%3};" \
        : "+f"((d)[0]), "+f"((d)[1]), "+f"((d)[2]), "+f"((d)[3]) \
        : "r"((a)[0]), "r"((a)[1]), "r"((a)[2]), "r"((a)[3]), \
          "r"((b)[0]), "r"((b)[1]))

#define LDSM_X4(r0, r1, r2, r3, addr) \
    asm volatile("ldmatrix.sync.aligned.m8n8.x4.shared.b16 {%0,%1,%2,%3}, [%4];" \
        : "=r"(r0), "=r"(r1), "=r"(r2), "=r"(r3) : "r"(addr))

__device__ __forceinline__ void bf16_split2(float2 f, uint32_t& hi, uint32_t& lo) {
    uint32_t h;
    asm("cvt.rn.bf16x2.f32 %0, %1, %2;" : "=r"(h) : "f"(f.y), "f"(f.x));
    float hx = __uint_as_float(h << 16);
    float hy = __uint_as_float(h & 0xffff0000u);
    asm("cvt.rn.bf16x2.f32 %0, %1, %2;" : "=r"(lo) : "f"(f.y - hy), "f"(f.x - hx));
    hi = h;
}

__device__ __forceinline__ float silu_f(float g) {
    return g / (1.f + __expf(-g));
}

// ---- routing ----
__global__ void zero_counts() {
    if (threadIdx.x < NEXP) g_cnt[threadIdx.x] = 0;
}

__global__ void router_kernel(const float* __restrict__ x,
                              const float* __restrict__ rw) {
    int t = blockIdx.x * blockDim.y + threadIdx.y;
    if (t >= T_TOK) return;
    int lane = threadIdx.x;
    float acc[NEXP];
#pragma unroll
    for (int e = 0; e < NEXP; e++) acc[e] = 0.f;
    const float* xr = x + (size_t)t * DDIM;
    for (int d = lane; d < DDIM; d += 32) {
        float xv = xr[d];
        const float4* r = (const float4*)(rw + (size_t)d * NEXP);
        float4 r0 = r[0], r1 = r[1];
        acc[0] += xv * r0.x; acc[1] += xv * r0.y;
        acc[2] += xv * r0.z; acc[3] += xv * r0.w;
        acc[4] += xv * r1.x; acc[5] += xv * r1.y;
        acc[6] += xv * r1.z; acc[7] += xv * r1.w;
    }
#pragma unroll
    for (int off = 16; off > 0; off >>= 1)
#pragma unroll
        for (int e = 0; e < NEXP; e++)
            acc[e] += __shfl_down_sync(0xffffffffu, acc[e], off);
    if (lane == 0) {
        int best = 0; float bv = acc[0];
#pragma unroll
        for (int e = 1; e < NEXP; e++)
            if (acc[e] > bv) { bv = acc[e]; best = e; }
        g_eid[t] = best;
        g_w[t]   = 1.f / (1.f + expf(-bv));
    }
}

__global__ void scatter_kernel() {
    int t = blockIdx.x * blockDim.x + threadIdx.x;
    if (t < T_TOK) {
        int e = g_eid[t];
        int p = atomicAdd(&g_cnt[e], 1);
        g_list[e * T_TOK + p] = t;
    }
}

__global__ void convert_x(const float* __restrict__ x) {
    int i = blockIdx.x * blockDim.x + threadIdx.x;   // over T*D/2
    float2 f = ((const float2*)x)[i];
    uint32_t hi, lo;
    bf16_split2(f, hi, lo);
    ((uint32_t*)g_xhi)[i] = hi;
    ((uint32_t*)g_xlo)[i] = lo;
}

// transpose + split: src [z][R][C] fp32 -> dst [z][C][R] bf16 hi/lo
__global__ void __launch_bounds__(256)
convert_wT(const float* __restrict__ src,
           __nv_bfloat16* __restrict__ dhi,
           __nv_bfloat16* __restrict__ dlo,
           int R, int C) {
    __shared__ float tile[64][65];
    int c0 = blockIdx.x * 64, r0 = blockIdx.y * 64;
    size_t sbase = (size_t)blockIdx.z * R * C;
    int tid = threadIdx.x;
#pragma unroll
    for (int i = 0; i < 16; i++) {
        int idx = tid + 256 * i;
        int r = idx >> 6, c = idx & 63;
        tile[r][c] = src[sbase + (size_t)(r0 + r) * C + c0 + c];
    }
    __syncthreads();
#pragma unroll
    for (int i = 0; i < 16; i++) {
        int idx = tid + 256 * i;
        int r = idx >> 6, c = idx & 63;
        float f = tile[c][r];
        __nv_bfloat16 h = __float2bfloat16(f);
        float fh = __bfloat162float(h);
        __nv_bfloat16 l = __float2bfloat16(f - fh);
        size_t o = sbase + (size_t)(c0 + r) * R + r0 + c;
        dhi[o] = h;
        dlo[o] = l;
    }
}

// ================= gate+up GEMM =================
template<bool SHARED>
__global__ void __launch_bounds__(256, 2)
gu_kernel(const __nv_bfloat16* __restrict__ bghi, const __nv_bfloat16* __restrict__ bglo,
          const __nv_bfloat16* __restrict__ buhi, const __nv_bfloat16* __restrict__ bulo,
          __nv_bfloat16* __restrict__ hhi, __nv_bfloat16* __restrict__ hlo) {
    int e   = SHARED ? 0 : blockIdx.z;
    int cnt = SHARED ? T_TOK : g_cnt[e];
    int m0  = blockIdx.x * 128;
    if (m0 >= cnt) return;
    int n0  = blockIdx.y * 64;

    extern __shared__ char dyn[];
    __shared__ int toks[128];
    int tid = threadIdx.x;
    if (tid < 128) {
        int m = m0 + tid;
        toks[tid] = (m < cnt) ? (SHARED ? m : g_list[e * T_TOK + m]) : -1;
    }
    __syncthreads();

    uint32_t smb = smem_u32(dyn);

    // A: 1 slot/thread/array (128 rows x 2 chunks of 16B)
    int arow = tid >> 1, achk = tid & 1;
    int atk = toks[arow];
    int apred = (atk >= 0) ? 16 : 0;
    size_t aoff = (atk >= 0) ? ((size_t)atk * DDIM + achk * 8) : 0;
    const __nv_bfloat16* ahsrc = g_xhi + aoff;
    const __nv_bfloat16* alsrc = g_xlo + aoff;
    uint32_t adst = arow * GU_AST + achk * 16;

    // B: 1 slot/thread/array (128 cols x 2 chunks); cols 0-63 gate, 64-127 up
    int bcol = tid >> 1, bchk = tid & 1;
    size_t boff = ((size_t)e * FDIM + n0 + (bcol & 63)) * DDIM + bchk * 8;
    const __nv_bfloat16* bhsrc = ((bcol < 64) ? bghi : buhi) + boff;
    const __nv_bfloat16* blsrc = ((bcol < 64) ? bglo : bulo) + boff;
    uint32_t bdst = bcol * GU_AST + bchk * 16;

    auto load_stage = [&](int kc) {
        int k0 = kc * GU_KC;
        int st = kc & (GU_NSTG - 1);
        cpa16(smb + GU_AHI + st * GU_ASTG + adst, ahsrc + k0, apred);
        cpa16(smb + GU_ALO + st * GU_ASTG + adst, alsrc + k0, apred);
        cpa16(smb + GU_BHI + st * GU_BSTG + bdst, bhsrc + k0, 16);
        cpa16(smb + GU_BLO + st * GU_BSTG + bdst, blsrc + k0, 16);
        CP_COMMIT();
    };

    int wid = tid >> 5, lane = tid & 31;
    int wm = (wid >> 1) * 32;
    int wn = (wid & 1) * 32;
    int gr = lane >> 2, gc = lane & 3;

    // ldmatrix lane offsets
    uint32_t a_loff[2];
#pragma unroll
    for (int mt = 0; mt < 2; mt++)
        a_loff[mt] = (wm + mt * 16 + (lane & 15)) * GU_AST + (lane >> 4) * 16;
    int bl8 = (lane & 7) + ((lane >> 4) << 3);
    uint32_t bko = ((lane >> 3) & 1) * 16;
    uint32_t b_loff[4];
    b_loff[0] = (wn + bl8) * GU_AST + bko;
    b_loff[1] = (wn + 16 + bl8) * GU_AST + bko;
    b_loff[2] = (64 + wn + bl8) * GU_AST + bko;
    b_loff[3] = (64 + wn + 16 + bl8) * GU_AST + bko;

    float acc[2][8][4];
#pragma unroll
    for (int mt = 0; mt < 2; mt++)
#pragma unroll
        for (int nt = 0; nt < 8; nt++)
#pragma unroll
            for (int j = 0; j < 4; j++) acc[mt][nt][j] = 0.f;

    const int NKC = DDIM / GU_KC;  // 128
    load_stage(0); load_stage(1); load_stage(2);

    for (int kc = 0; kc < NKC; kc++) {
        asm volatile("cp.async.wait_group 2;" ::: "memory");
        __syncthreads();
        if (kc + 3 < NKC) load_stage(kc + 3);

        int st = kc & (GU_NSTG - 1);
        uint32_t ah = smb + GU_AHI + st * GU_ASTG;
        uint32_t al = smb + GU_ALO + st * GU_ASTG;
        uint32_t bh = smb + GU_BHI + st * GU_BSTG;
        uint32_t bl = smb + GU_BLO + st * GU_BSTG;

        uint32_t a_hi[2][4], a_lo[2][4];
#pragma unroll
        for (int mt = 0; mt < 2; mt++) {
            LDSM_X4(a_hi[mt][0], a_hi[mt][1], a_hi[mt][2], a_hi[mt][3], ah + a_loff[mt]);
            LDSM_X4(a_lo[mt][0], a_lo[mt][1], a_lo[mt][2], a_lo[mt][3], al + a_loff[mt]);
        }
#pragma unroll
        for (int p = 0; p < 4; p++) {
            uint32_t bhp[4], blp[4];
            LDSM_X4(bhp[0], bhp[1], bhp[2], bhp[3], bh + b_loff[p]);
            LDSM_X4(blp[0], blp[1], blp[2], blp[3], bl + b_loff[p]);
#pragma unroll
            for (int half = 0; half < 2; half++) {
                int nt = p * 2 + half;
                uint32_t* bhx = bhp + half * 2;
                uint32_t* blx = blp + half * 2;
#pragma unroll
                for (int mt = 0; mt < 2; mt++) {
                    MMA_BF16(acc[mt][nt], a_hi[mt], blx);
                    MMA_BF16(acc[mt][nt], a_lo[mt], bhx);
                    MMA_BF16(acc[mt][nt], a_hi[mt], bhx);
                }
            }
        }
    }

    // epilogue: silu(gate)*up -> h hi/lo bf16
    uint32_t* hh = (uint32_t*)hhi;
    uint32_t* hl = (uint32_t*)hlo;
#pragma unroll
    for (int mt = 0; mt < 2; mt++) {
#pragma unroll
        for (int half = 0; half < 2; half++) {
            int row = wm + mt * 16 + gr + half * 8;
            int tk = toks[row];
            if (tk < 0) continue;
            size_t rb = ((size_t)tk * FDIM + n0 + wn) >> 1;
#pragma unroll
            for (int nt = 0; nt < 4; nt++) {
                float2 v;
                v.x = silu_f(acc[mt][nt][half * 2 + 0]) * acc[mt][nt + 4][half * 2 + 0];
                v.y = silu_f(acc[mt][nt][half * 2 + 1]) * acc[mt][nt + 4][half * 2 + 1];
                uint32_t hi, lo;
                bf16_split2(v, hi, lo);
                size_t idx = rb + ((nt * 8 + gc * 2) >> 1);
                hh[idx] = hi;
                hl[idx] = lo;
            }
        }
    }
}

// ================= down GEMM =================
template<bool SHARED>
__global__ void __launch_bounds__(256, 2)
dn_kernel(const __nv_bfloat16* __restrict__ hinhi,
          const __nv_bfloat16* __restrict__ hinlo,
          const __nv_bfloat16* __restrict__ bdhi,
          const __nv_bfloat16* __restrict__ bdlo,
          float* __restrict__ out) {
    int e   = SHARED ? 0 : blockIdx.z;
    int cnt = SHARED ? T_TOK : g_cnt[e];
    int m0  = blockIdx.x * 128;
    if (m0 >= cnt) return;
    int n0  = blockIdx.y * 64;

    extern __shared__ char dyn[];
    __shared__ int toks[128];
    int tid = threadIdx.x;
    if (tid < 128) {
        int m = m0 + tid;
        toks[tid] = (m < cnt) ? (SHARED ? m : g_list[e * T_TOK + m]) : -1;
    }
    __syncthreads();

    uint32_t smb = smem_u32(dyn);

    // A: 2 slots/thread/array (128 rows x 4 chunks)
    const __nv_bfloat16* ahsrc[2];
    const __nv_bfloat16* alsrc[2];
    int apred[2];
    uint32_t adst[2];
#pragma unroll
    for (int i = 0; i < 2; i++) {
        int s = tid * 2 + i;
        int row = s >> 2, q = s & 3;
        int tk = toks[row];
        apred[i] = (tk >= 0) ? 16 : 0;
        size_t off = (tk >= 0) ? ((size_t)tk * FDIM + q * 8) : 0;
        ahsrc[i] = hinhi + off;
        alsrc[i] = hinlo + off;
        adst[i]  = row * DN_AST + q * 16;
    }
    // B: 1 slot/thread/array (64 cols x 4 chunks)
    int bcol = tid >> 2, bchk = tid & 3;
    size_t boff = ((size_t)e * DDIM + n0 + bcol) * FDIM + bchk * 8;
    const __nv_bfloat16* bhsrc = bdhi + boff;
    const __nv_bfloat16* blsrc = bdlo + boff;
    uint32_t bdst = bcol * DN_AST + bchk * 16;

    auto load_stage = [&](int kc, int st) {
        int k0 = kc * DN_KC;
#pragma unroll
        for (int i = 0; i < 2; i++) {
            cpa16(smb + DN_AHI + st * DN_ASTG + adst[i], ahsrc[i] + k0, apred[i]);
            cpa16(smb + DN_ALO + st * DN_ASTG + adst[i], alsrc[i] + k0, apred[i]);
        }
        cpa16(smb + DN_BHI + st * DN_BSTG + bdst, bhsrc + k0, 16);
        cpa16(smb + DN_BLO + st * DN_BSTG + bdst, blsrc + k0, 16);
        CP_COMMIT();
    };

    int wid = tid >> 5, lane = tid & 31;
    int wm = (wid >> 1) * 32;
    int wn = (wid & 1) * 32;
    int gr = lane >> 2, gc = lane & 3;

    uint32_t a_loff[2];
#pragma unroll
    for (int mt = 0; mt < 2; mt++)
        a_loff[mt] = (wm + mt * 16 + (lane & 15)) * DN_AST + (lane >> 4) * 16;
    int bl8 = (lane & 7) + ((lane >> 4) << 3);
    uint32_t bko = ((lane >> 3) & 1) * 16;
    uint32_t b_loff[2];
    b_loff[0] = (wn + bl8) * DN_AST + bko;
    b_loff[1] = (wn + 16 + bl8) * DN_AST + bko;

    float acc[2][4][4];
#pragma unroll
    for (int mt = 0; mt < 2; mt++)
#pragma unroll
        for (int nt = 0; nt < 4; nt++)
#pragma unroll
            for (int j = 0; j < 4; j++) acc[mt][nt][j] = 0.f;

    const int NKC = FDIM / DN_KC;  // 128
    load_stage(0, 0); load_stage(1, 1);

    for (int kc = 0; kc < NKC; kc++) {
        asm volatile("cp.async.wait_group 1;" ::: "memory");
        __syncthreads();
        if (kc + 2 < NKC) load_stage(kc + 2, (kc + 2) % DN_NSTG);

        int st = kc % DN_NSTG;
        uint32_t ah = smb + DN_AHI + st * DN_ASTG;
        uint32_t al = smb + DN_ALO + st * DN_ASTG;
        uint32_t bh = smb + DN_BHI + st * DN_BSTG;
        uint32_t bl = smb + DN_BLO + st * DN_BSTG;

#pragma unroll
        for (int ks = 0; ks < 2; ks++) {
            uint32_t kso = ks * 32;
            uint32_t a_hi[2][4], a_lo[2][4];
#pragma unroll
            for (int mt = 0; mt < 2; mt++) {
                LDSM_X4(a_hi[mt][0], a_hi[mt][1], a_hi[mt][2], a_hi[mt][3], ah + a_loff[mt] + kso);
                LDSM_X4(a_lo[mt][0], a_lo[mt][1], a_lo[mt][2], a_lo[mt][3], al + a_loff[mt] + kso);
            }
#pragma unroll
            for (int p = 0; p < 2; p++) {
                uint32_t bhp[4], blp[4];
                LDSM_X4(bhp[0], bhp[1], bhp[2], bhp[3], bh + b_loff[p] + kso);
                LDSM_X4(blp[0], blp[1], blp[2], blp[3], bl + b_loff[p] + kso);
#pragma unroll
                for (int half = 0; half < 2; half++) {
                    int nt = p * 2 + half;
                    uint32_t* bhx = bhp + half * 2;
                    uint32_t* blx = blp + half * 2;
#pragma unroll
                    for (int mt = 0; mt < 2; mt++) {
                        MMA_BF16(acc[mt][nt], a_hi[mt], blx);
                        MMA_BF16(acc[mt][nt], a_lo[mt], bhx);
                        MMA_BF16(acc[mt][nt], a_hi[mt], bhx);
                    }
                }
            }
        }
    }

#pragma unroll
    for (int mt = 0; mt < 2; mt++) {
#pragma unroll
        for (int half = 0; half < 2; half++) {
            int row = wm + mt * 16 + gr + half * 8;
            int tk = toks[row];
            if (tk < 0) continue;
            float wt = SHARED ? 1.f : g_w[tk];
            float* orow = out + (size_t)tk * DDIM + n0 + wn;
#pragma unroll
            for (int nt = 0; nt < 4; nt++) {
                float2 v;
                v.x = wt * acc[mt][nt][half * 2 + 0];
                v.y = wt * acc[mt][nt][half * 2 + 1];
                float* op = orow + nt * 8 + gc * 2;
                if (SHARED) {
                    float2 p = *(float2*)op;
                    v.x += p.x; v.y += p.y;
                }
                *(float2*)op = v;
            }
        }
    }
}

// ================= host =================
extern "C" void kernel_launch(void* const* d_in, const int* in_sizes, int n_in,
                              void* d_out, int out_size) {
    const float* x   = (const float*)d_in[0];
    const float* rw  = (const float*)d_in[1];
    const float* wg  = (const float*)d_in[2];
    const float* wu  = (const float*)d_in[3];
    const float* wd  = (const float*)d_in[4];
    const float* wsg = (const float*)d_in[5];
    const float* wsu = (const float*)d_in[6];
    const float* wsd = (const float*)d_in[7];
    float* out = (float*)d_out;

    void *p_hhi, *p_hlo, *p_hshi, *p_hslo;
    void *p_wghi, *p_wglo, *p_wuhi, *p_wulo, *p_wdhi, *p_wdlo;
    void *p_wsghi, *p_wsglo, *p_wsuhi, *p_wsulo, *p_wsdhi, *p_wsdlo;
    cudaGetSymbolAddress(&p_hhi, g_hhi);
    cudaGetSymbolAddress(&p_hlo, g_hlo);
    cudaGetSymbolAddress(&p_hshi, g_hshi);
    cudaGetSymbolAddress(&p_hslo, g_hslo);
    cudaGetSymbolAddress(&p_wghi, g_wgThi);
    cudaGetSymbolAddress(&p_wglo, g_wgTlo);
    cudaGetSymbolAddress(&p_wuhi, g_wuThi);
    cudaGetSymbolAddress(&p_wulo, g_wuTlo);
    cudaGetSymbolAddress(&p_wdhi, g_wdThi);
    cudaGetSymbolAddress(&p_wdlo, g_wdTlo);
    cudaGetSymbolAddress(&p_wsghi, g_wsgThi);
    cudaGetSymbolAddress(&p_wsglo, g_wsgTlo);
    cudaGetSymbolAddress(&p_wsuhi, g_wsuThi);
    cudaGetSymbolAddress(&p_wsulo, g_wsuTlo);
    cudaGetSymbolAddress(&p_wsdhi, g_wsdThi);
    cudaGetSymbolAddress(&p_wsdlo, g_wsdTlo);

    cudaFuncSetAttribute(gu_kernel<false>, cudaFuncAttributeMaxDynamicSharedMemorySize, SMEM_GU);
    cudaFuncSetAttribute(gu_kernel<true>,  cudaFuncAttributeMaxDynamicSharedMemorySize, SMEM_GU);
    cudaFuncSetAttribute(dn_kernel<false>, cudaFuncAttributeMaxDynamicSharedMemorySize, SMEM_DN);
    cudaFuncSetAttribute(dn_kernel<true>,  cudaFuncAttributeMaxDynamicSharedMemorySize, SMEM_DN);

    zero_counts<<<1, 32>>>();
    router_kernel<<<T_TOK / 8, dim3(32, 8)>>>(x, rw);
    scatter_kernel<<<T_TOK / 256, 256>>>();
    convert_x<<<T_TOK * DDIM / 2 / 256, 256>>>(x);

    // weight transpose+split (src [z][R][C] -> dst [z][C][R])
    convert_wT<<<dim3(FDIM / 64, DDIM / 64, NEXP), 256>>>(wg,  (__nv_bfloat16*)p_wghi, (__nv_bfloat16*)p_wglo, DDIM, FDIM);
    convert_wT<<<dim3(FDIM / 64, DDIM / 64, NEXP), 256>>>(wu,  (__nv_bfloat16*)p_wuhi, (__nv_bfloat16*)p_wulo, DDIM, FDIM);
    convert_wT<<<dim3(DDIM / 64, FDIM / 64, NEXP), 256>>>(wd,  (__nv_bfloat16*)p_wdhi, (__nv_bfloat16*)p_wdlo, FDIM, DDIM);
    convert_wT<<<dim3(FDIM / 64, DDIM / 64, 1),    256>>>(wsg, (__nv_bfloat16*)p_wsghi, (__nv_bfloat16*)p_wsglo, DDIM, FDIM);
    convert_wT<<<dim3(FDIM / 64, DDIM / 64, 1),    256>>>(wsu, (__nv_bfloat16*)p_wsuhi, (__nv_bfloat16*)p_wsulo, DDIM, FDIM);
    convert_wT<<<dim3(DDIM / 64, FDIM / 64, 1),    256>>>(wsd, (__nv_bfloat16*)p_wsdhi, (__nv_bfloat16*)p_wsdlo, FDIM, DDIM);

    gu_kernel<false><<<dim3(T_TOK / 128, FDIM / 64, NEXP), 256, SMEM_GU>>>(
        (const __nv_bfloat16*)p_wghi, (const __nv_bfloat16*)p_wglo,
        (const __nv_bfloat16*)p_wuhi, (const __nv_bfloat16*)p_wulo,
        (__nv_bfloat16*)p_hhi, (__nv_bfloat16*)p_hlo);
    dn_kernel<false><<<dim3(T_TOK / 128, DDIM / 64, NEXP), 256, SMEM_DN>>>(
        (const __nv_bfloat16*)p_hhi, (const __nv_bfloat16*)p_hlo,
        (const __nv_bfloat16*)p_wdhi, (const __nv_bfloat16*)p_wdlo, out);

    gu_kernel<true><<<dim3(T_TOK / 128, FDIM / 64, 1), 256, SMEM_GU>>>(
        (const __nv_bfloat16*)p_wsghi, (const __nv_bfloat16*)p_wsglo,
        (const __nv_bfloat16*)p_wsuhi, (const __nv_bfloat16*)p_wsulo,
        (__nv_bfloat16*)p_hshi, (__nv_bfloat16*)p_hslo);
    dn_kernel<true><<<dim3(T_TOK / 128, DDIM / 64, 1), 256, SMEM_DN>>>(
        (const __nv_bfloat16*)p_hshi, (const __nv_bfloat16*)p_hslo,
        (const __nv_bfloat16*)p_wsdhi, (const __nv_bfloat16*)p_wsdlo, out);
}

// round 10
// speedup vs baseline: 1.2421x; 1.2421x over previous
#include <cuda_runtime.h>
#include <cuda_bf16.h>
#include <math.h>
#include <stdint.h>

#define T_TOK 2048
#define DDIM  2048
#define FDIM  4096
#define NEXP  8

// ---------- gu geometry: KC 16, NSTG 4 ----------
#define GU_NSTG 4
#define GU_KC   16
#define GU_AST  48                    // A row bytes (32 data + 16 pad)
#define GU_BST  272                   // B k-row bytes (256 data + 16 pad)
#define GU_ASTG (128 * GU_AST)        // 6144
#define GU_BSTG (GU_KC * GU_BST)      // 4352
#define GU_AHI  0
#define GU_ALO  (GU_NSTG * GU_ASTG)
#define GU_BHI  (2 * GU_NSTG * GU_ASTG)
#define GU_BLO  (GU_BHI + GU_NSTG * GU_BSTG)
#define SMEM_GU (GU_BLO + GU_NSTG * GU_BSTG)   // 83968

// ---------- dn geometry: KC 32, NSTG 3 ----------
#define DN_NSTG 3
#define DN_KC   32
#define DN_AST  80
#define DN_BST  144                   // 128 data + 16 pad
#define DN_ASTG (128 * DN_AST)        // 10240
#define DN_BSTG (DN_KC * DN_BST)      // 4608
#define DN_AHI  0
#define DN_ALO  (DN_NSTG * DN_ASTG)
#define DN_BHI  (2 * DN_NSTG * DN_ASTG)
#define DN_BLO  (DN_BHI + DN_NSTG * DN_BSTG)
#define SMEM_DN (DN_BLO + DN_NSTG * DN_BSTG)   // 89088

#define WD_ELEMS ((size_t)NEXP * FDIM * DDIM)  // 67108864

// ---- static scratch ----
__device__ int   g_cnt[NEXP];
__device__ int   g_eid[T_TOK];
__device__ float g_w[T_TOK];
__device__ int   g_list[NEXP * T_TOK];
__device__ __align__(16) __nv_bfloat16 g_xhi[(size_t)T_TOK * DDIM];
__device__ __align__(16) __nv_bfloat16 g_xlo[(size_t)T_TOK * DDIM];
__device__ __align__(16) __nv_bfloat16 g_hhi[(size_t)T_TOK * FDIM];
__device__ __align__(16) __nv_bfloat16 g_hlo[(size_t)T_TOK * FDIM];
__device__ __align__(16) __nv_bfloat16 g_hshi[(size_t)T_TOK * FDIM];
__device__ __align__(16) __nv_bfloat16 g_hslo[(size_t)T_TOK * FDIM];
// pre-split weights, NATIVE [z][k][n] layout (no transpose)
__device__ __align__(16) __nv_bfloat16 g_wghi[(size_t)NEXP * DDIM * FDIM];
__device__ __align__(16) __nv_bfloat16 g_wglo[(size_t)NEXP * DDIM * FDIM];
__device__ __align__(16) __nv_bfloat16 g_wuhi[(size_t)NEXP * DDIM * FDIM];
__device__ __align__(16) __nv_bfloat16 g_wulo[(size_t)NEXP * DDIM * FDIM];
__device__ __align__(16) __nv_bfloat16 g_wdhi[(size_t)NEXP * FDIM * DDIM];
__device__ __align__(16) __nv_bfloat16 g_wdlo[(size_t)NEXP * FDIM * DDIM];
__device__ __align__(16) __nv_bfloat16 g_wsghi[(size_t)DDIM * FDIM];
__device__ __align__(16) __nv_bfloat16 g_wsglo[(size_t)DDIM * FDIM];
__device__ __align__(16) __nv_bfloat16 g_wsuhi[(size_t)DDIM * FDIM];
__device__ __align__(16) __nv_bfloat16 g_wsulo[(size_t)DDIM * FDIM];
__device__ __align__(16) __nv_bfloat16 g_wsdhi[(size_t)FDIM * DDIM];
__device__ __align__(16) __nv_bfloat16 g_wsdlo[(size_t)FDIM * DDIM];

// ---- helpers ----
__device__ __forceinline__ uint32_t smem_u32(const void* p) {
    uint32_t a;
    asm("{ .reg .u64 t; cvta.to.shared.u64 t, %1; cvt.u32.u64 %0, t; }"
        : "=r"(a) : "l"(p));
    return a;
}

__device__ __forceinline__ void cpa16(uint32_t dst, const void* src, int srcsz) {
    asm volatile("cp.async.cg.shared.global [%0], [%1], 16, %2;"
                 :: "r"(dst), "l"(src), "r"(srcsz) : "memory");
}
#define CP_COMMIT() asm volatile("cp.async.commit_group;" ::: "memory")

#define MMA_BF16(d, a, b) \
    asm volatile("mma.sync.aligned.m16n8k16.row.col.f32.bf16.bf16.f32 " \
        "{%0,%1,%2,%3}, {%4,%5,%6,%7}, {%8,%9}, {%0,%1,%2,%3};" \
        : "+f"((d)[0]), "+f"((d)[1]), "+f"((d)[2]), "+f"((d)[3]) \
        : "r"((a)[0]), "r"((a)[1]), "r"((a)[2]), "r"((a)[3]), \
          "r"((b)[0]), "r"((b)[1]))

#define LDSM_X4(r0, r1, r2, r3, addr) \
    asm volatile("ldmatrix.sync.aligned.m8n8.x4.shared.b16 {%0,%1,%2,%3}, [%4];" \
        : "=r"(r0), "=r"(r1), "=r"(r2), "=r"(r3) : "r"(addr))

#define LDSM_X4T(r0, r1, r2, r3, addr) \
    asm volatile("ldmatrix.sync.aligned.m8n8.x4.trans.shared.b16 {%0,%1,%2,%3}, [%4];" \
        : "=r"(r0), "=r"(r1), "=r"(r2), "=r"(r3) : "r"(addr))

__device__ __forceinline__ void bf16_split2(float2 f, uint32_t& hi, uint32_t& lo) {
    uint32_t h;
    asm("cvt.rn.bf16x2.f32 %0, %1, %2;" : "=r"(h) : "f"(f.y), "f"(f.x));
    float hx = __uint_as_float(h << 16);
    float hy = __uint_as_float(h & 0xffff0000u);
    asm("cvt.rn.bf16x2.f32 %0, %1, %2;" : "=r"(lo) : "f"(f.y - hy), "f"(f.x - hx));
    hi = h;
}

__device__ __forceinline__ float silu_f(float g) {
    return g / (1.f + __expf(-g));
}

// convert 8 consecutive floats at src+off into hi/lo bf16 (uint4 stores)
__device__ __forceinline__ void conv8(const float* src, __nv_bfloat16* dhi,
                                      __nv_bfloat16* dlo, size_t off) {
    float4 a = *(const float4*)(src + off);
    float4 b = *(const float4*)(src + off + 4);
    uint32_t h0, l0, h1, l1, h2, l2, h3, l3;
    bf16_split2(make_float2(a.x, a.y), h0, l0);
    bf16_split2(make_float2(a.z, a.w), h1, l1);
    bf16_split2(make_float2(b.x, b.y), h2, l2);
    bf16_split2(make_float2(b.z, b.w), h3, l3);
    *(uint4*)(dhi + off) = make_uint4(h0, h1, h2, h3);
    *(uint4*)(dlo + off) = make_uint4(l0, l1, l2, l3);
}

// ---- routing / setup ----
__global__ void zero_counts() {
    if (threadIdx.x < NEXP) g_cnt[threadIdx.x] = 0;
}

__global__ void router_kernel(const float* __restrict__ x,
                              const float* __restrict__ rw) {
    int t = blockIdx.x * blockDim.y + threadIdx.y;
    if (t >= T_TOK) return;
    int lane = threadIdx.x;
    float acc[NEXP];
#pragma unroll
    for (int e = 0; e < NEXP; e++) acc[e] = 0.f;
    const float* xr = x + (size_t)t * DDIM;
    for (int d = lane; d < DDIM; d += 32) {
        float xv = xr[d];
        const float4* r = (const float4*)(rw + (size_t)d * NEXP);
        float4 r0 = r[0], r1 = r[1];
        acc[0] += xv * r0.x; acc[1] += xv * r0.y;
        acc[2] += xv * r0.z; acc[3] += xv * r0.w;
        acc[4] += xv * r1.x; acc[5] += xv * r1.y;
        acc[6] += xv * r1.z; acc[7] += xv * r1.w;
    }
#pragma unroll
    for (int off = 16; off > 0; off >>= 1)
#pragma unroll
        for (int e = 0; e < NEXP; e++)
            acc[e] += __shfl_down_sync(0xffffffffu, acc[e], off);
    if (lane == 0) {
        int best = 0; float bv = acc[0];
#pragma unroll
        for (int e = 1; e < NEXP; e++)
            if (acc[e] > bv) { bv = acc[e]; best = e; }
        g_eid[t] = best;
        g_w[t]   = 1.f / (1.f + expf(-bv));
    }
}

__global__ void scatter_kernel() {
    int t = blockIdx.x * blockDim.x + threadIdx.x;
    if (t < T_TOK) {
        int e = g_eid[t];
        int p = atomicAdd(&g_cnt[e], 1);
        g_list[e * T_TOK + p] = t;
    }
}

__global__ void convert_x(const float* __restrict__ x) {
    size_t off = ((size_t)blockIdx.x * 256 + threadIdx.x) * 8;
    conv8(x, g_xhi, g_xlo, off);
}

// streaming weight convert (no transpose): 2048 elems per block
__global__ void __launch_bounds__(256)
convert_w(const float* __restrict__ src,
          __nv_bfloat16* __restrict__ dhi,
          __nv_bfloat16* __restrict__ dlo) {
    size_t off = ((size_t)blockIdx.x * 256 + threadIdx.x) * 8;
    conv8(src, dhi, dlo, off);
}

__global__ void zero_out(float4* out) {
    out[(size_t)blockIdx.x * 256 + threadIdx.x] = make_float4(0.f, 0.f, 0.f, 0.f);
}

// ================= gate+up GEMM (merged routed+shared + wd conversion) =================
__global__ void __launch_bounds__(256, 2)
gu_kernel(const float* __restrict__ wd, const float* __restrict__ wsd) {
    int tid = threadIdx.x;

    // ---- folded wd/wsd conversion blocks ----
    if (blockIdx.y >= 64) {
        int cid = (blockIdx.y - 64) + 8 * (blockIdx.x + 16 * blockIdx.z); // 0..1151
        size_t base = (size_t)cid * 65536;
#pragma unroll 4
        for (int it = 0; it < 32; it++) {
            size_t e0 = base + (size_t)it * 2048 + (size_t)tid * 8;
            if (e0 < WD_ELEMS) conv8(wd, g_wdhi, g_wdlo, e0);
            else               conv8(wsd, g_wsdhi, g_wsdlo, e0 - WD_ELEMS);
        }
        return;
    }

    int e   = blockIdx.z;          // 0..7 routed, 8 shared
    bool sh = (e == 8);
    int cnt = sh ? T_TOK : g_cnt[e];
    int m0  = blockIdx.x * 128;
    if (m0 >= cnt) return;
    int n0  = blockIdx.y * 64;

    const __nv_bfloat16* bgh = sh ? g_wsghi : g_wghi + (size_t)e * DDIM * FDIM;
    const __nv_bfloat16* bgl = sh ? g_wsglo : g_wglo + (size_t)e * DDIM * FDIM;
    const __nv_bfloat16* buh = sh ? g_wsuhi : g_wuhi + (size_t)e * DDIM * FDIM;
    const __nv_bfloat16* bul = sh ? g_wsulo : g_wulo + (size_t)e * DDIM * FDIM;
    __nv_bfloat16* hhi = sh ? g_hshi : g_hhi;
    __nv_bfloat16* hlo = sh ? g_hslo : g_hlo;

    extern __shared__ char dyn[];
    __shared__ int toks[128];
    if (tid < 128) {
        int m = m0 + tid;
        toks[tid] = (m < cnt) ? (sh ? m : g_list[e * T_TOK + m]) : -1;
    }
    __syncthreads();

    uint32_t smb = smem_u32(dyn);

    // A loads: 256 chunks of 16B per array (128 rows x 2 chunks)
    int arow = tid >> 1, achk = tid & 1;
    int atk = toks[arow];
    int apred = (atk >= 0) ? 16 : 0;
    size_t aoff = (atk >= 0) ? ((size_t)atk * DDIM + achk * 8) : 0;
    const __nv_bfloat16* ahsrc = g_xhi + aoff;
    const __nv_bfloat16* alsrc = g_xlo + aoff;
    uint32_t adst = arow * GU_AST + achk * 16;

    // B loads: 16 k-rows x 16 chunks (chk<8 gate, else up), native [k][n]
    int brow = tid >> 4, bchk = tid & 15;
    size_t boff = (size_t)brow * FDIM + n0 + (bchk & 7) * 8;
    const __nv_bfloat16* bhsrc = ((bchk < 8) ? bgh : buh) + boff;
    const __nv_bfloat16* blsrc = ((bchk < 8) ? bgl : bul) + boff;
    uint32_t bdst = brow * GU_BST + bchk * 16;

    auto load_stage = [&](int kc) {
        int st = kc & (GU_NSTG - 1);
        int k0 = kc * GU_KC;
        cpa16(smb + GU_AHI + st * GU_ASTG + adst, ahsrc + k0, apred);
        cpa16(smb + GU_ALO + st * GU_ASTG + adst, alsrc + k0, apred);
        cpa16(smb + GU_BHI + st * GU_BSTG + bdst, bhsrc + (size_t)k0 * FDIM, 16);
        cpa16(smb + GU_BLO + st * GU_BSTG + bdst, blsrc + (size_t)k0 * FDIM, 16);
        CP_COMMIT();
    };

    int wid = tid >> 5, lane = tid & 31;
    int wm = (wid >> 1) * 32;
    int wn = (wid & 1) * 32;
    int gr = lane >> 2, gc = lane & 3;

    // ldmatrix lane offsets
    uint32_t a_loff[2];
#pragma unroll
    for (int mt = 0; mt < 2; mt++)
        a_loff[mt] = (wm + mt * 16 + (lane & 15)) * GU_AST + (lane >> 4) * 16;
    // B trans: t = lane/8; k_off = (t&1)*8 + lane%8; n_rel = (t>>1)*8
    int bt = lane >> 3;
    uint32_t b_lane = ((bt & 1) * 8 + (lane & 7)) * GU_BST + ((bt >> 1) * 8) * 2;

    float acc[2][8][4];
#pragma unroll
    for (int mt = 0; mt < 2; mt++)
#pragma unroll
        for (int nt = 0; nt < 8; nt++)
#pragma unroll
            for (int j = 0; j < 4; j++) acc[mt][nt][j] = 0.f;

    const int NKC = DDIM / GU_KC;  // 128
    load_stage(0); load_stage(1); load_stage(2);

    for (int kc = 0; kc < NKC; kc++) {
        asm volatile("cp.async.wait_group 2;" ::: "memory");
        __syncthreads();
        if (kc + 3 < NKC) load_stage(kc + 3);

        int st = kc & (GU_NSTG - 1);
        uint32_t ah = smb + GU_AHI + st * GU_ASTG;
        uint32_t al = smb + GU_ALO + st * GU_ASTG;
        uint32_t bh = smb + GU_BHI + st * GU_BSTG;
        uint32_t bl = smb + GU_BLO + st * GU_BSTG;

        uint32_t a_hi[2][4], a_lo[2][4];
#pragma unroll
        for (int mt = 0; mt < 2; mt++) {
            LDSM_X4(a_hi[mt][0], a_hi[mt][1], a_hi[mt][2], a_hi[mt][3], ah + a_loff[mt]);
            LDSM_X4(a_lo[mt][0], a_lo[mt][1], a_lo[mt][2], a_lo[mt][3], al + a_loff[mt]);
        }
#pragma unroll
        for (int half = 0; half < 2; half++) {
#pragma unroll
            for (int p = 0; p < 2; p++) {
                uint32_t nb2 = (half * 64 + wn + p * 16) * 2;
                uint32_t bhp[4], blp[4];
                LDSM_X4T(bhp[0], bhp[1], bhp[2], bhp[3], bh + b_lane + nb2);
                LDSM_X4T(blp[0], blp[1], blp[2], blp[3], bl + b_lane + nb2);
#pragma unroll
                for (int g = 0; g < 2; g++) {
                    int nt = half * 4 + p * 2 + g;
                    uint32_t* bhx = bhp + g * 2;
                    uint32_t* blx = blp + g * 2;
#pragma unroll
                    for (int mt = 0; mt < 2; mt++) {
                        MMA_BF16(acc[mt][nt], a_hi[mt], blx);
                        MMA_BF16(acc[mt][nt], a_lo[mt], bhx);
                        MMA_BF16(acc[mt][nt], a_hi[mt], bhx);
                    }
                }
            }
        }
    }

    // epilogue: silu(gate)*up -> h hi/lo
    uint32_t* hh = (uint32_t*)hhi;
    uint32_t* hl = (uint32_t*)hlo;
#pragma unroll
    for (int mt = 0; mt < 2; mt++) {
#pragma unroll
        for (int half = 0; half < 2; half++) {
            int row = wm + mt * 16 + gr + half * 8;
            int tk = toks[row];
            if (tk < 0) continue;
            size_t rb = ((size_t)tk * FDIM + n0 + wn) >> 1;
#pragma unroll
            for (int nt = 0; nt < 4; nt++) {
                float2 v;
                v.x = silu_f(acc[mt][nt][half * 2 + 0]) * acc[mt][nt + 4][half * 2 + 0];
                v.y = silu_f(acc[mt][nt][half * 2 + 1]) * acc[mt][nt + 4][half * 2 + 1];
                uint32_t hi, lo;
                bf16_split2(v, hi, lo);
                size_t idx = rb + ((nt * 8 + gc * 2) >> 1);
                hh[idx] = hi;
                hl[idx] = lo;
            }
        }
    }
}

// ================= down GEMM (merged routed+shared, atomic epilogue) =================
__global__ void __launch_bounds__(256, 2)
dn_kernel(float* __restrict__ out) {
    int tid = threadIdx.x;
    int e   = blockIdx.z;
    bool sh = (e == 8);
    int cnt = sh ? T_TOK : g_cnt[e];
    int m0  = blockIdx.x * 128;
    if (m0 >= cnt) return;
    int n0  = blockIdx.y * 64;

    const __nv_bfloat16* bdh = sh ? g_wsdhi : g_wdhi + (size_t)e * FDIM * DDIM;
    const __nv_bfloat16* bdl = sh ? g_wsdlo : g_wdlo + (size_t)e * FDIM * DDIM;
    const __nv_bfloat16* hih = sh ? g_hshi : g_hhi;
    const __nv_bfloat16* hil = sh ? g_hslo : g_hlo;

    extern __shared__ char dyn[];
    __shared__ int toks[128];
    if (tid < 128) {
        int m = m0 + tid;
        toks[tid] = (m < cnt) ? (sh ? m : g_list[e * T_TOK + m]) : -1;
    }
    __syncthreads();

    uint32_t smb = smem_u32(dyn);

    // A: 512 chunks per array, 2/thread
    const __nv_bfloat16* ahsrc[2];
    const __nv_bfloat16* alsrc[2];
    int apred[2];
    uint32_t adst[2];
#pragma unroll
    for (int i = 0; i < 2; i++) {
        int s = tid + 256 * i;
        int row = s >> 2, chk = s & 3;
        int tk = toks[row];
        apred[i] = (tk >= 0) ? 16 : 0;
        size_t off = (tk >= 0) ? ((size_t)tk * FDIM + chk * 8) : 0;
        ahsrc[i] = hih + off;
        alsrc[i] = hil + off;
        adst[i]  = row * DN_AST + chk * 16;
    }
    // B: 32 k-rows x 8 chunks, native [k][n]
    int brow = tid >> 3, bchk = tid & 7;
    size_t boff = (size_t)brow * DDIM + n0 + bchk * 8;
    const __nv_bfloat16* bhsrc = bdh + boff;
    const __nv_bfloat16* blsrc = bdl + boff;
    uint32_t bdst = brow * DN_BST + bchk * 16;

    auto load_stage = [&](int kc, int st) {
        int k0 = kc * DN_KC;
#pragma unroll
        for (int i = 0; i < 2; i++) {
            cpa16(smb + DN_AHI + st * DN_ASTG + adst[i], ahsrc[i] + k0, apred[i]);
            cpa16(smb + DN_ALO + st * DN_ASTG + adst[i], alsrc[i] + k0, apred[i]);
        }
        cpa16(smb + DN_BHI + st * DN_BSTG + bdst, bhsrc + (size_t)k0 * DDIM, 16);
        cpa16(smb + DN_BLO + st * DN_BSTG + bdst, blsrc + (size_t)k0 * DDIM, 16);
        CP_COMMIT();
    };

    int wid = tid >> 5, lane = tid & 31;
    int wm = (wid >> 1) * 32;
    int wn = (wid & 1) * 32;
    int gr = lane >> 2, gc = lane & 3;

    uint32_t a_loff[2];
#pragma unroll
    for (int mt = 0; mt < 2; mt++)
        a_loff[mt] = (wm + mt * 16 + (lane & 15)) * DN_AST + (lane >> 4) * 16;
    int bt = lane >> 3;
    uint32_t b_lane = ((bt & 1) * 8 + (lane & 7)) * DN_BST + ((bt >> 1) * 8) * 2;

    float acc[2][4][4];
#pragma unroll
    for (int mt = 0; mt < 2; mt++)
#pragma unroll
        for (int nt = 0; nt < 4; nt++)
#pragma unroll
            for (int j = 0; j < 4; j++) acc[mt][nt][j] = 0.f;

    const int NKC = FDIM / DN_KC;  // 128
    load_stage(0, 0); load_stage(1, 1);

    for (int kc = 0; kc < NKC; kc++) {
        asm volatile("cp.async.wait_group 1;" ::: "memory");
        __syncthreads();
        if (kc + 2 < NKC) load_stage(kc + 2, (kc + 2) % DN_NSTG);

        int st = kc % DN_NSTG;
        uint32_t ah = smb + DN_AHI + st * DN_ASTG;
        uint32_t al = smb + DN_ALO + st * DN_ASTG;
        uint32_t bh = smb + DN_BHI + st * DN_BSTG;
        uint32_t bl = smb + DN_BLO + st * DN_BSTG;

#pragma unroll
        for (int ks = 0; ks < 2; ks++) {
            uint32_t kao = ks * 32;             // A: 16 k elems = 32 B
            uint32_t kbo = ks * 16 * DN_BST;    // B: 16 k rows
            uint32_t a_hi[2][4], a_lo[2][4];
#pragma unroll
            for (int mt = 0; mt < 2; mt++) {
                LDSM_X4(a_hi[mt][0], a_hi[mt][1], a_hi[mt][2], a_hi[mt][3], ah + a_loff[mt] + kao);
                LDSM_X4(a_lo[mt][0], a_lo[mt][1], a_lo[mt][2], a_lo[mt][3], al + a_loff[mt] + kao);
            }
#pragma unroll
            for (int p = 0; p < 2; p++) {
                uint32_t nb2 = (wn + p * 16) * 2;
                uint32_t bhp[4], blp[4];
                LDSM_X4T(bhp[0], bhp[1], bhp[2], bhp[3], bh + b_lane + kbo + nb2);
                LDSM_X4T(blp[0], blp[1], blp[2], blp[3], bl + b_lane + kbo + nb2);
#pragma unroll
                for (int g = 0; g < 2; g++) {
                    int nt = p * 2 + g;
                    uint32_t* bhx = bhp + g * 2;
                    uint32_t* blx = blp + g * 2;
#pragma unroll
                    for (int mt = 0; mt < 2; mt++) {
                        MMA_BF16(acc[mt][nt], a_hi[mt], blx);
                        MMA_BF16(acc[mt][nt], a_lo[mt], bhx);
                        MMA_BF16(acc[mt][nt], a_hi[mt], bhx);
                    }
                }
            }
        }
    }

    // epilogue: atomic accumulate (out pre-zeroed; exactly 2 commutative adds/elem)
#pragma unroll
    for (int mt = 0; mt < 2; mt++) {
#pragma unroll
        for (int half = 0; half < 2; half++) {
            int row = wm + mt * 16 + gr + half * 8;
            int tk = toks[row];
            if (tk < 0) continue;
            float wt = sh ? 1.f : g_w[tk];
            float* orow = out + (size_t)tk * DDIM + n0 + wn;
#pragma unroll
            for (int nt = 0; nt < 4; nt++) {
                float* op = orow + nt * 8 + gc * 2;
                atomicAdd(op,     wt * acc[mt][nt][half * 2 + 0]);
                atomicAdd(op + 1, wt * acc[mt][nt][half * 2 + 1]);
            }
        }
    }
}

// ================= host =================
extern "C" void kernel_launch(void* const* d_in, const int* in_sizes, int n_in,
                              void* d_out, int out_size) {
    const float* x   = (const float*)d_in[0];
    const float* rw  = (const float*)d_in[1];
    const float* wg  = (const float*)d_in[2];
    const float* wu  = (const float*)d_in[3];
    const float* wd  = (const float*)d_in[4];
    const float* wsg = (const float*)d_in[5];
    const float* wsu = (const float*)d_in[6];
    const float* wsd = (const float*)d_in[7];
    float* out = (float*)d_out;

    void *p_wghi, *p_wglo, *p_wuhi, *p_wulo;
    void *p_wsghi, *p_wsglo, *p_wsuhi, *p_wsulo;
    cudaGetSymbolAddress(&p_wghi, g_wghi);
    cudaGetSymbolAddress(&p_wglo, g_wglo);
    cudaGetSymbolAddress(&p_wuhi, g_wuhi);
    cudaGetSymbolAddress(&p_wulo, g_wulo);
    cudaGetSymbolAddress(&p_wsghi, g_wsghi);
    cudaGetSymbolAddress(&p_wsglo, g_wsglo);
    cudaGetSymbolAddress(&p_wsuhi, g_wsuhi);
    cudaGetSymbolAddress(&p_wsulo, g_wsulo);

    cudaFuncSetAttribute(gu_kernel, cudaFuncAttributeMaxDynamicSharedMemorySize, SMEM_GU);
    cudaFuncSetAttribute(dn_kernel, cudaFuncAttributeMaxDynamicSharedMemorySize, SMEM_DN);

    zero_counts<<<1, 32>>>();
    router_kernel<<<T_TOK / 8, dim3(32, 8)>>>(x, rw);
    scatter_kernel<<<T_TOK / 256, 256>>>();
    convert_x<<<(int)((size_t)T_TOK * DDIM / 2048), 256>>>(x);
    zero_out<<<(int)((size_t)T_TOK * DDIM / 1024), 256>>>((float4*)out);

    // streaming converts for gate/up (down weights converted inside gu launch)
    convert_w<<<(int)((size_t)NEXP * DDIM * FDIM / 2048), 256>>>(
        wg, (__nv_bfloat16*)p_wghi, (__nv_bfloat16*)p_wglo);
    convert_w<<<(int)((size_t)NEXP * DDIM * FDIM / 2048), 256>>>(
        wu, (__nv_bfloat16*)p_wuhi, (__nv_bfloat16*)p_wulo);
    convert_w<<<(int)((size_t)DDIM * FDIM / 2048), 256>>>(
        wsg, (__nv_bfloat16*)p_wsghi, (__nv_bfloat16*)p_wsglo);
    convert_w<<<(int)((size_t)DDIM * FDIM / 2048), 256>>>(
        wsu, (__nv_bfloat16*)p_wsuhi, (__nv_bfloat16*)p_wsulo);

    // gu: y<64 gemm tiles (z=0..7 routed, 8 shared); y in [64,72) -> wd/wsd conversion
    gu_kernel<<<dim3(16, 72, 9), 256, SMEM_GU>>>(wd, wsd);
    dn_kernel<<<dim3(16, 32, 9), 256, SMEM_DN>>>(out);
}

// round 11
// speedup vs baseline: 1.2452x; 1.0025x over previous
#include <cuda_runtime.h>
#include <cuda_bf16.h>
#include <math.h>
#include <stdint.h>

#define T_TOK 2048
#define DDIM  2048
#define FDIM  4096
#define NEXP  8

// ---------- gu geometry: KC 32, NSTG 3 ----------
#define GU_NSTG 3
#define GU_KC   32
#define GU_AST  80                    // A row: 64 B data + 16 pad
#define GU_BST  272                   // B k-row: 256 B data + 16 pad
#define GU_ASTG (128 * GU_AST)        // 10240
#define GU_BSTG (GU_KC * GU_BST)      // 8704
#define GU_AHI  0
#define GU_ALO  (GU_NSTG * GU_ASTG)             // 30720
#define GU_BHI  (2 * GU_NSTG * GU_ASTG)         // 61440
#define GU_BLO  (GU_BHI + GU_NSTG * GU_BSTG)    // 87552
#define SMEM_GU (GU_BLO + GU_NSTG * GU_BSTG)    // 113664

// ---------- dn geometry: KC 32, NSTG 3 ----------
#define DN_NSTG 3
#define DN_KC   32
#define DN_AST  80
#define DN_BST  144
#define DN_ASTG (128 * DN_AST)
#define DN_BSTG (DN_KC * DN_BST)
#define DN_AHI  0
#define DN_ALO  (DN_NSTG * DN_ASTG)
#define DN_BHI  (2 * DN_NSTG * DN_ASTG)
#define DN_BLO  (DN_BHI + DN_NSTG * DN_BSTG)
#define SMEM_DN (DN_BLO + DN_NSTG * DN_BSTG)    // 89088

#define WGU_ELEMS ((size_t)NEXP * DDIM * FDIM)  // 67108864 (per tensor)
#define WD_ELEMS  ((size_t)NEXP * FDIM * DDIM)

// ---- static scratch ----
__device__ int   g_cnt[NEXP];
__device__ int   g_eid[T_TOK];
__device__ float g_w[T_TOK];
__device__ int   g_list[NEXP * T_TOK];
__device__ __align__(16) __nv_bfloat16 g_xhi[(size_t)T_TOK * DDIM];
__device__ __align__(16) __nv_bfloat16 g_xlo[(size_t)T_TOK * DDIM];
__device__ __align__(16) __nv_bfloat16 g_hhi[(size_t)T_TOK * FDIM];
__device__ __align__(16) __nv_bfloat16 g_hlo[(size_t)T_TOK * FDIM];
__device__ __align__(16) __nv_bfloat16 g_hshi[(size_t)T_TOK * FDIM];
__device__ __align__(16) __nv_bfloat16 g_hslo[(size_t)T_TOK * FDIM];
// pre-split weights, NATIVE [z][k][n] layout
__device__ __align__(16) __nv_bfloat16 g_wghi[(size_t)NEXP * DDIM * FDIM];
__device__ __align__(16) __nv_bfloat16 g_wglo[(size_t)NEXP * DDIM * FDIM];
__device__ __align__(16) __nv_bfloat16 g_wuhi[(size_t)NEXP * DDIM * FDIM];
__device__ __align__(16) __nv_bfloat16 g_wulo[(size_t)NEXP * DDIM * FDIM];
__device__ __align__(16) __nv_bfloat16 g_wdhi[(size_t)NEXP * FDIM * DDIM];
__device__ __align__(16) __nv_bfloat16 g_wdlo[(size_t)NEXP * FDIM * DDIM];
__device__ __align__(16) __nv_bfloat16 g_wsghi[(size_t)DDIM * FDIM];
__device__ __align__(16) __nv_bfloat16 g_wsglo[(size_t)DDIM * FDIM];
__device__ __align__(16) __nv_bfloat16 g_wsuhi[(size_t)DDIM * FDIM];
__device__ __align__(16) __nv_bfloat16 g_wsulo[(size_t)DDIM * FDIM];
__device__ __align__(16) __nv_bfloat16 g_wsdhi[(size_t)FDIM * DDIM];
__device__ __align__(16) __nv_bfloat16 g_wsdlo[(size_t)FDIM * DDIM];

// ---- helpers ----
__device__ __forceinline__ uint32_t smem_u32(const void* p) {
    uint32_t a;
    asm("{ .reg .u64 t; cvta.to.shared.u64 t, %1; cvt.u32.u64 %0, t; }"
        : "=r"(a) : "l"(p));
    return a;
}

__device__ __forceinline__ void cpa16(uint32_t dst, const void* src, int srcsz) {
    asm volatile("cp.async.cg.shared.global [%0], [%1], 16, %2;"
                 :: "r"(dst), "l"(src), "r"(srcsz) : "memory");
}
#define CP_COMMIT() asm volatile("cp.async.commit_group;" ::: "memory")

#define MMA_BF16(d, a, b) \
    asm volatile("mma.sync.aligned.m16n8k16.row.col.f32.bf16.bf16.f32 " \
        "{%0,%1,%2,%3}, {%4,%5,%6,%7}, {%8,%9}, {%0,%1,%2,%3};" \
        : "+f"((d)[0]), "+f"((d)[1]), "+f"((d)[2]), "+f"((d)[3]) \
        : "r"((a)[0]), "r"((a)[1]), "r"((a)[2]), "r"((a)[3]), \
          "r"((b)[0]), "r"((b)[1]))

#define LDSM_X4(r0, r1, r2, r3, addr) \
    asm volatile("ldmatrix.sync.aligned.m8n8.x4.shared.b16 {%0,%1,%2,%3}, [%4];" \
        : "=r"(r0), "=r"(r1), "=r"(r2), "=r"(r3) : "r"(addr))

#define LDSM_X4T(r0, r1, r2, r3, addr) \
    asm volatile("ldmatrix.sync.aligned.m8n8.x4.trans.shared.b16 {%0,%1,%2,%3}, [%4];" \
        : "=r"(r0), "=r"(r1), "=r"(r2), "=r"(r3) : "r"(addr))

__device__ __forceinline__ void bf16_split2(float2 f, uint32_t& hi, uint32_t& lo) {
    uint32_t h;
    asm("cvt.rn.bf16x2.f32 %0, %1, %2;" : "=r"(h) : "f"(f.y), "f"(f.x));
    float hx = __uint_as_float(h << 16);
    float hy = __uint_as_float(h & 0xffff0000u);
    asm("cvt.rn.bf16x2.f32 %0, %1, %2;" : "=r"(lo) : "f"(f.y - hy), "f"(f.x - hx));
    hi = h;
}

__device__ __forceinline__ float silu_f(float g) {
    return g / (1.f + __expf(-g));
}

__device__ __forceinline__ void conv8(const float* src, __nv_bfloat16* dhi,
                                      __nv_bfloat16* dlo, size_t off) {
    float4 a = *(const float4*)(src + off);
    float4 b = *(const float4*)(src + off + 4);
    uint32_t h0, l0, h1, l1, h2, l2, h3, l3;
    bf16_split2(make_float2(a.x, a.y), h0, l0);
    bf16_split2(make_float2(a.z, a.w), h1, l1);
    bf16_split2(make_float2(b.x, b.y), h2, l2);
    bf16_split2(make_float2(b.z, b.w), h3, l3);
    *(uint4*)(dhi + off) = make_uint4(h0, h1, h2, h3);
    *(uint4*)(dlo + off) = make_uint4(l0, l1, l2, l3);
}

// ---- routing / setup ----
__global__ void zero_counts() {
    if (threadIdx.x < NEXP) g_cnt[threadIdx.x] = 0;
}

__global__ void router_kernel(const float* __restrict__ x,
                              const float* __restrict__ rw) {
    int t = blockIdx.x * blockDim.y + threadIdx.y;
    if (t >= T_TOK) return;
    int lane = threadIdx.x;
    float acc[NEXP];
#pragma unroll
    for (int e = 0; e < NEXP; e++) acc[e] = 0.f;
    const float* xr = x + (size_t)t * DDIM;
    for (int d = lane; d < DDIM; d += 32) {
        float xv = xr[d];
        const float4* r = (const float4*)(rw + (size_t)d * NEXP);
        float4 r0 = r[0], r1 = r[1];
        acc[0] += xv * r0.x; acc[1] += xv * r0.y;
        acc[2] += xv * r0.z; acc[3] += xv * r0.w;
        acc[4] += xv * r1.x; acc[5] += xv * r1.y;
        acc[6] += xv * r1.z; acc[7] += xv * r1.w;
    }
#pragma unroll
    for (int off = 16; off > 0; off >>= 1)
#pragma unroll
        for (int e = 0; e < NEXP; e++)
            acc[e] += __shfl_down_sync(0xffffffffu, acc[e], off);
    if (lane == 0) {
        int best = 0; float bv = acc[0];
#pragma unroll
        for (int e = 1; e < NEXP; e++)
            if (acc[e] > bv) { bv = acc[e]; best = e; }
        g_eid[t] = best;
        g_w[t]   = 1.f / (1.f + expf(-bv));
    }
}

__global__ void scatter_kernel() {
    int t = blockIdx.x * blockDim.x + threadIdx.x;
    if (t < T_TOK) {
        int e = g_eid[t];
        int p = atomicAdd(&g_cnt[e], 1);
        g_list[e * T_TOK + p] = t;
    }
}

__global__ void convert_x(const float* __restrict__ x) {
    size_t off = ((size_t)blockIdx.x * 256 + threadIdx.x) * 8;
    conv8(x, g_xhi, g_xlo, off);
}

// wsg+wsu converted up front (small, ~25us)
__global__ void __launch_bounds__(256)
convert_wsgu(const float* __restrict__ wsg, const float* __restrict__ wsu) {
    size_t off = ((size_t)blockIdx.x * 256 + threadIdx.x) * 8;
    const size_t N = (size_t)DDIM * FDIM;
    if (off < N) conv8(wsg, g_wsghi, g_wsglo, off);
    else         conv8(wsu, g_wsuhi, g_wsulo, off - N);
}

__global__ void zero_out(float4* out) {
    out[(size_t)blockIdx.x * 256 + threadIdx.x] = make_float4(0.f, 0.f, 0.f, 0.f);
}

// ================= gate+up GEMM =================
// SHARED variant: gemm on shared expert (wsg/wsu pre-converted); folded blocks
//   convert wg/wu (cv0, cv1).
// Routed variant: gemm on routed experts (wg/wu now pre-converted); folded
//   blocks convert wd/wsd (cv0, cv1).
template<bool SHARED>
__global__ void __launch_bounds__(256, 2)
gu_kernel(const float* __restrict__ cv0, const float* __restrict__ cv1) {
    int tid = threadIdx.x;

    if (blockIdx.y >= 64) {
        if (SHARED) {
            int cid = (blockIdx.y - 64) * 16 + blockIdx.x;      // 0..2047
            size_t base = (size_t)cid * 65536;
#pragma unroll 4
            for (int it = 0; it < 32; it++) {
                size_t e0 = base + (size_t)it * 2048 + (size_t)tid * 8;
                if (e0 < WGU_ELEMS) conv8(cv0, g_wghi, g_wglo, e0);
                else                conv8(cv1, g_wuhi, g_wulo, e0 - WGU_ELEMS);
            }
        } else {
            int cid = (blockIdx.y - 64) + 9 * (blockIdx.x + 16 * blockIdx.z); // 0..1151
            size_t base = (size_t)cid * 65536;
#pragma unroll 4
            for (int it = 0; it < 32; it++) {
                size_t e0 = base + (size_t)it * 2048 + (size_t)tid * 8;
                if (e0 < WD_ELEMS) conv8(cv0, g_wdhi, g_wdlo, e0);
                else               conv8(cv1, g_wsdhi, g_wsdlo, e0 - WD_ELEMS);
            }
        }
        return;
    }

    int e   = SHARED ? 0 : blockIdx.z;
    int cnt = SHARED ? T_TOK : g_cnt[e];
    int m0  = blockIdx.x * 128;
    if (m0 >= cnt) return;
    int n0  = blockIdx.y * 64;

    const __nv_bfloat16* bgh = SHARED ? g_wsghi : g_wghi + (size_t)e * DDIM * FDIM;
    const __nv_bfloat16* bgl = SHARED ? g_wsglo : g_wglo + (size_t)e * DDIM * FDIM;
    const __nv_bfloat16* buh = SHARED ? g_wsuhi : g_wuhi + (size_t)e * DDIM * FDIM;
    const __nv_bfloat16* bul = SHARED ? g_wsulo : g_wulo + (size_t)e * DDIM * FDIM;
    __nv_bfloat16* hhi = SHARED ? g_hshi : g_hhi;
    __nv_bfloat16* hlo = SHARED ? g_hslo : g_hlo;

    extern __shared__ char dyn[];
    __shared__ int toks[128];
    if (tid < 128) {
        int m = m0 + tid;
        toks[tid] = (m < cnt) ? (SHARED ? m : g_list[e * T_TOK + m]) : -1;
    }
    __syncthreads();

    uint32_t smb = smem_u32(dyn);

    // A loads: 128 rows x 4 chunks of 16B per array -> 512 chunks, 2/thread
    const __nv_bfloat16* ahsrc[2];
    const __nv_bfloat16* alsrc[2];
    int apred[2];
    uint32_t adst[2];
#pragma unroll
    for (int i = 0; i < 2; i++) {
        int s = tid + 256 * i;
        int row = s >> 2, chk = s & 3;
        int tk = toks[row];
        apred[i] = (tk >= 0) ? 16 : 0;
        size_t off = (tk >= 0) ? ((size_t)tk * DDIM + chk * 8) : 0;
        ahsrc[i] = g_xhi + off;
        alsrc[i] = g_xlo + off;
        adst[i]  = row * GU_AST + chk * 16;
    }
    // B loads: 32 k-rows x 16 chunks (chk<8 gate, else up) -> 512 chunks, 2/thread
    const __nv_bfloat16* bhsrc[2];
    const __nv_bfloat16* blsrc[2];
    uint32_t bdst[2];
#pragma unroll
    for (int i = 0; i < 2; i++) {
        int s = tid + 256 * i;
        int brow = s >> 4, bchk = s & 15;
        size_t boff = (size_t)brow * FDIM + n0 + (bchk & 7) * 8;
        bhsrc[i] = ((bchk < 8) ? bgh : buh) + boff;
        blsrc[i] = ((bchk < 8) ? bgl : bul) + boff;
        bdst[i]  = brow * GU_BST + bchk * 16;
    }

    auto load_stage = [&](int kc, int st) {
        int k0 = kc * GU_KC;
#pragma unroll
        for (int i = 0; i < 2; i++) {
            cpa16(smb + GU_AHI + st * GU_ASTG + adst[i], ahsrc[i] + k0, apred[i]);
            cpa16(smb + GU_ALO + st * GU_ASTG + adst[i], alsrc[i] + k0, apred[i]);
        }
#pragma unroll
        for (int i = 0; i < 2; i++) {
            cpa16(smb + GU_BHI + st * GU_BSTG + bdst[i], bhsrc[i] + (size_t)k0 * FDIM, 16);
            cpa16(smb + GU_BLO + st * GU_BSTG + bdst[i], blsrc[i] + (size_t)k0 * FDIM, 16);
        }
        CP_COMMIT();
    };

    int wid = tid >> 5, lane = tid & 31;
    int wm = (wid >> 1) * 32;
    int wn = (wid & 1) * 32;
    int gr = lane >> 2, gc = lane & 3;

    uint32_t a_loff[2];
#pragma unroll
    for (int mt = 0; mt < 2; mt++)
        a_loff[mt] = (wm + mt * 16 + (lane & 15)) * GU_AST + (lane >> 4) * 16;
    int bt = lane >> 3;
    uint32_t b_lane = ((bt & 1) * 8 + (lane & 7)) * GU_BST + ((bt >> 1) * 8) * 2;

    float acc[2][8][4];
#pragma unroll
    for (int mt = 0; mt < 2; mt++)
#pragma unroll
        for (int nt = 0; nt < 8; nt++)
#pragma unroll
            for (int j = 0; j < 4; j++) acc[mt][nt][j] = 0.f;

    const int NKC = DDIM / GU_KC;  // 64
    load_stage(0, 0); load_stage(1, 1);

    for (int kc = 0; kc < NKC; kc++) {
        asm volatile("cp.async.wait_group 1;" ::: "memory");
        __syncthreads();
        if (kc + 2 < NKC) load_stage(kc + 2, (kc + 2) % GU_NSTG);

        int st = kc % GU_NSTG;
        uint32_t ah = smb + GU_AHI + st * GU_ASTG;
        uint32_t al = smb + GU_ALO + st * GU_ASTG;
        uint32_t bh = smb + GU_BHI + st * GU_BSTG;
        uint32_t bl = smb + GU_BLO + st * GU_BSTG;

#pragma unroll
        for (int ks = 0; ks < 2; ks++) {
            uint32_t kao = ks * 32;
            uint32_t kbo = ks * 16 * GU_BST;
            uint32_t a_hi[2][4], a_lo[2][4];
#pragma unroll
            for (int mt = 0; mt < 2; mt++) {
                LDSM_X4(a_hi[mt][0], a_hi[mt][1], a_hi[mt][2], a_hi[mt][3], ah + a_loff[mt] + kao);
                LDSM_X4(a_lo[mt][0], a_lo[mt][1], a_lo[mt][2], a_lo[mt][3], al + a_loff[mt] + kao);
            }
#pragma unroll
            for (int half = 0; half < 2; half++) {
#pragma unroll
                for (int p = 0; p < 2; p++) {
                    uint32_t nb2 = (half * 64 + wn + p * 16) * 2;
                    uint32_t bhp[4], blp[4];
                    LDSM_X4T(bhp[0], bhp[1], bhp[2], bhp[3], bh + b_lane + kbo + nb2);
                    LDSM_X4T(blp[0], blp[1], blp[2], blp[3], bl + b_lane + kbo + nb2);
#pragma unroll
                    for (int g = 0; g < 2; g++) {
                        int nt = half * 4 + p * 2 + g;
                        uint32_t* bhx = bhp + g * 2;
                        uint32_t* blx = blp + g * 2;
#pragma unroll
                        for (int mt = 0; mt < 2; mt++) {
                            MMA_BF16(acc[mt][nt], a_hi[mt], blx);
                            MMA_BF16(acc[mt][nt], a_lo[mt], bhx);
                            MMA_BF16(acc[mt][nt], a_hi[mt], bhx);
                        }
                    }
                }
            }
        }
    }

    uint32_t* hh = (uint32_t*)hhi;
    uint32_t* hl = (uint32_t*)hlo;
#pragma unroll
    for (int mt = 0; mt < 2; mt++) {
#pragma unroll
        for (int half = 0; half < 2; half++) {
            int row = wm + mt * 16 + gr + half * 8;
            int tk = toks[row];
            if (tk < 0) continue;
            size_t rb = ((size_t)tk * FDIM + n0 + wn) >> 1;
#pragma unroll
            for (int nt = 0; nt < 4; nt++) {
                float2 v;
                v.x = silu_f(acc[mt][nt][half * 2 + 0]) * acc[mt][nt + 4][half * 2 + 0];
                v.y = silu_f(acc[mt][nt][half * 2 + 1]) * acc[mt][nt + 4][half * 2 + 1];
                uint32_t hi, lo;
                bf16_split2(v, hi, lo);
                size_t idx = rb + ((nt * 8 + gc * 2) >> 1);
                hh[idx] = hi;
                hl[idx] = lo;
            }
        }
    }
}

// ================= down GEMM (merged routed+shared, atomic epilogue) =================
__global__ void __launch_bounds__(256, 2)
dn_kernel(float* __restrict__ out) {
    int tid = threadIdx.x;
    int e   = blockIdx.z;
    bool sh = (e == 8);
    int cnt = sh ? T_TOK : g_cnt[e];
    int m0  = blockIdx.x * 128;
    if (m0 >= cnt) return;
    int n0  = blockIdx.y * 64;

    const __nv_bfloat16* bdh = sh ? g_wsdhi : g_wdhi + (size_t)e * FDIM * DDIM;
    const __nv_bfloat16* bdl = sh ? g_wsdlo : g_wdlo + (size_t)e * FDIM * DDIM;
    const __nv_bfloat16* hih = sh ? g_hshi : g_hhi;
    const __nv_bfloat16* hil = sh ? g_hslo : g_hlo;

    extern __shared__ char dyn[];
    __shared__ int toks[128];
    if (tid < 128) {
        int m = m0 + tid;
        toks[tid] = (m < cnt) ? (sh ? m : g_list[e * T_TOK + m]) : -1;
    }
    __syncthreads();

    uint32_t smb = smem_u32(dyn);

    const __nv_bfloat16* ahsrc[2];
    const __nv_bfloat16* alsrc[2];
    int apred[2];
    uint32_t adst[2];
#pragma unroll
    for (int i = 0; i < 2; i++) {
        int s = tid + 256 * i;
        int row = s >> 2, chk = s & 3;
        int tk = toks[row];
        apred[i] = (tk >= 0) ? 16 : 0;
        size_t off = (tk >= 0) ? ((size_t)tk * FDIM + chk * 8) : 0;
        ahsrc[i] = hih + off;
        alsrc[i] = hil + off;
        adst[i]  = row * DN_AST + chk * 16;
    }
    int brow = tid >> 3, bchk = tid & 7;
    size_t boff = (size_t)brow * DDIM + n0 + bchk * 8;
    const __nv_bfloat16* bhsrc = bdh + boff;
    const __nv_bfloat16* blsrc = bdl + boff;
    uint32_t bdst = brow * DN_BST + bchk * 16;

    auto load_stage = [&](int kc, int st) {
        int k0 = kc * DN_KC;
#pragma unroll
        for (int i = 0; i < 2; i++) {
            cpa16(smb + DN_AHI + st * DN_ASTG + adst[i], ahsrc[i] + k0, apred[i]);
            cpa16(smb + DN_ALO + st * DN_ASTG + adst[i], alsrc[i] + k0, apred[i]);
        }
        cpa16(smb + DN_BHI + st * DN_BSTG + bdst, bhsrc + (size_t)k0 * DDIM, 16);
        cpa16(smb + DN_BLO + st * DN_BSTG + bdst, blsrc + (size_t)k0 * DDIM, 16);
        CP_COMMIT();
    };

    int wid = tid >> 5, lane = tid & 31;
    int wm = (wid >> 1) * 32;
    int wn = (wid & 1) * 32;
    int gr = lane >> 2, gc = lane & 3;

    uint32_t a_loff[2];
#pragma unroll
    for (int mt = 0; mt < 2; mt++)
        a_loff[mt] = (wm + mt * 16 + (lane & 15)) * DN_AST + (lane >> 4) * 16;
    int bt = lane >> 3;
    uint32_t b_lane = ((bt & 1) * 8 + (lane & 7)) * DN_BST + ((bt >> 1) * 8) * 2;

    float acc[2][4][4];
#pragma unroll
    for (int mt = 0; mt < 2; mt++)
#pragma unroll
        for (int nt = 0; nt < 4; nt++)
#pragma unroll
            for (int j = 0; j < 4; j++) acc[mt][nt][j] = 0.f;

    const int NKC = FDIM / DN_KC;  // 128
    load_stage(0, 0); load_stage(1, 1);

    for (int kc = 0; kc < NKC; kc++) {
        asm volatile("cp.async.wait_group 1;" ::: "memory");
        __syncthreads();
        if (kc + 2 < NKC) load_stage(kc + 2, (kc + 2) % DN_NSTG);

        int st = kc % DN_NSTG;
        uint32_t ah = smb + DN_AHI + st * DN_ASTG;
        uint32_t al = smb + DN_ALO + st * DN_ASTG;
        uint32_t bh = smb + DN_BHI + st * DN_BSTG;
        uint32_t bl = smb + DN_BLO + st * DN_BSTG;

#pragma unroll
        for (int ks = 0; ks < 2; ks++) {
            uint32_t kao = ks * 32;
            uint32_t kbo = ks * 16 * DN_BST;
            uint32_t a_hi[2][4], a_lo[2][4];
#pragma unroll
            for (int mt = 0; mt < 2; mt++) {
                LDSM_X4(a_hi[mt][0], a_hi[mt][1], a_hi[mt][2], a_hi[mt][3], ah + a_loff[mt] + kao);
                LDSM_X4(a_lo[mt][0], a_lo[mt][1], a_lo[mt][2], a_lo[mt][3], al + a_loff[mt] + kao);
            }
#pragma unroll
            for (int p = 0; p < 2; p++) {
                uint32_t nb2 = (wn + p * 16) * 2;
                uint32_t bhp[4], blp[4];
                LDSM_X4T(bhp[0], bhp[1], bhp[2], bhp[3], bh + b_lane + kbo + nb2);
                LDSM_X4T(blp[0], blp[1], blp[2], blp[3], bl + b_lane + kbo + nb2);
#pragma unroll
                for (int g = 0; g < 2; g++) {
                    int nt = p * 2 + g;
                    uint32_t* bhx = bhp + g * 2;
                    uint32_t* blx = blp + g * 2;
#pragma unroll
                    for (int mt = 0; mt < 2; mt++) {
                        MMA_BF16(acc[mt][nt], a_hi[mt], blx);
                        MMA_BF16(acc[mt][nt], a_lo[mt], bhx);
                        MMA_BF16(acc[mt][nt], a_hi[mt], bhx);
                    }
                }
            }
        }
    }

#pragma unroll
    for (int mt = 0; mt < 2; mt++) {
#pragma unroll
        for (int half = 0; half < 2; half++) {
            int row = wm + mt * 16 + gr + half * 8;
            int tk = toks[row];
            if (tk < 0) continue;
            float wt = sh ? 1.f : g_w[tk];
            float* orow = out + (size_t)tk * DDIM + n0 + wn;
#pragma unroll
            for (int nt = 0; nt < 4; nt++) {
                float* op = orow + nt * 8 + gc * 2;
                atomicAdd(op,     wt * acc[mt][nt][half * 2 + 0]);
                atomicAdd(op + 1, wt * acc[mt][nt][half * 2 + 1]);
            }
        }
    }
}

// ================= host =================
extern "C" void kernel_launch(void* const* d_in, const int* in_sizes, int n_in,
                              void* d_out, int out_size) {
    const float* x   = (const float*)d_in[0];
    const float* rw  = (const float*)d_in[1];
    const float* wg  = (const float*)d_in[2];
    const float* wu  = (const float*)d_in[3];
    const float* wd  = (const float*)d_in[4];
    const float* wsg = (const float*)d_in[5];
    const float* wsu = (const float*)d_in[6];
    const float* wsd = (const float*)d_in[7];
    float* out = (float*)d_out;

    cudaFuncSetAttribute(gu_kernel<true>,  cudaFuncAttributeMaxDynamicSharedMemorySize, SMEM_GU);
    cudaFuncSetAttribute(gu_kernel<false>, cudaFuncAttributeMaxDynamicSharedMemorySize, SMEM_GU);
    cudaFuncSetAttribute(dn_kernel, cudaFuncAttributeMaxDynamicSharedMemorySize, SMEM_DN);

    zero_counts<<<1, 32>>>();
    router_kernel<<<T_TOK / 8, dim3(32, 8)>>>(x, rw);
    scatter_kernel<<<T_TOK / 256, 256>>>();
    convert_x<<<(int)((size_t)T_TOK * DDIM / 2048), 256>>>(x);
    zero_out<<<(int)((size_t)T_TOK * DDIM / 1024), 256>>>((float4*)out);
    convert_wsgu<<<(int)(2 * (size_t)DDIM * FDIM / 2048), 256>>>(wsg, wsu);

    // shared-expert gu + folded wg/wu conversion (y in [64,192): 2048 conv blocks)
    gu_kernel<true><<<dim3(16, 192, 1), 256, SMEM_GU>>>(wg, wu);
    // routed gu + folded wd/wsd conversion (y in [64,73): 1152 conv blocks)
    gu_kernel<false><<<dim3(16, 73, NEXP), 256, SMEM_GU>>>(wd, wsd);
    // merged down (z=0..7 routed, 8 shared)
    dn_kernel<<<dim3(16, 32, 9), 256, SMEM_DN>>>(out);
}